// round 17
// baseline (speedup 1.0000x reference)
#include <cuda_runtime.h>
#include <cuda_fp16.h>
#include <cstdint>

#define B_    2
#define L_    2048
#define D_    1024
#define H_    16
#define HD_   64
#define MTOK  (B_ * L_)      // 4096

// ---------------------------------------------------------------------------
// Scratch (device globals)
// ---------------------------------------------------------------------------
__device__ __half g_x[(size_t)MTOK * D_];
__device__ __half g_qkv[(size_t)MTOK * (3 * D_)];
__device__ __half g_attn[(size_t)MTOK * D_];
__device__ __half g_wqkv[(size_t)(3 * D_) * D_];   // [N,K] fp16
__device__ __half g_wproj[(size_t)D_ * D_];        // [N,K] fp16

// ---------------------------------------------------------------------------
// Portable ISA helpers
// ---------------------------------------------------------------------------
__device__ __forceinline__ uint32_t smem_u32(const void* p) {
    uint32_t a;
    asm("{ .reg .u64 t; cvta.to.shared.u64 t, %1; cvt.u32.u64 %0, t; }" : "=r"(a) : "l"(p));
    return a;
}

#define CPASYNC16(dst, src) \
    asm volatile("cp.async.cg.shared.global [%0], [%1], 16;" :: "r"(dst), "l"(src))
#define CPCOMMIT() asm volatile("cp.async.commit_group;" ::: "memory")
#define CPWAIT(n)  asm volatile("cp.async.wait_group %0;" :: "n"(n) : "memory")

__device__ __forceinline__ void mma_f16(float* c, const uint32_t* a, const uint32_t* b) {
    asm volatile(
        "mma.sync.aligned.m16n8k16.row.col.f32.f16.f16.f32 "
        "{%0,%1,%2,%3},{%4,%5,%6,%7},{%8,%9},{%0,%1,%2,%3};"
        : "+f"(c[0]), "+f"(c[1]), "+f"(c[2]), "+f"(c[3])
        : "r"(a[0]), "r"(a[1]), "r"(a[2]), "r"(a[3]), "r"(b[0]), "r"(b[1]));
}

// fp16-accumulator variant: D/C are 2 regs (d0 = row g, d1 = row g+8)
__device__ __forceinline__ void mma_f16h(uint32_t* d, const uint32_t* a, const uint32_t* b) {
    asm volatile(
        "mma.sync.aligned.m16n8k16.row.col.f16.f16.f16.f16 "
        "{%0,%1},{%2,%3,%4,%5},{%6,%7},{%0,%1};"
        : "+r"(d[0]), "+r"(d[1])
        : "r"(a[0]), "r"(a[1]), "r"(a[2]), "r"(a[3]), "r"(b[0]), "r"(b[1]));
}

#define LDMX4(r, addr) \
    asm volatile("ldmatrix.sync.aligned.m8n8.x4.shared.b16 {%0,%1,%2,%3}, [%4];" \
        : "=r"((r)[0]), "=r"((r)[1]), "=r"((r)[2]), "=r"((r)[3]) : "r"(addr))

#define LDMX4_TRANS(r0, r1, r2, r3, addr) \
    asm volatile("ldmatrix.sync.aligned.m8n8.x4.trans.shared.b16 {%0,%1,%2,%3}, [%4];" \
        : "=r"(r0), "=r"(r1), "=r"(r2), "=r"(r3) : "r"(addr))

#define EX2F16X2(r) asm("ex2.approx.f16x2 %0, %0;" : "+r"(r))
#define HMUL2(r, m) asm("mul.f16x2 %0, %0, %1;" : "+r"(r) : "r"(m))
#define HADD2(a, b) asm("add.f16x2 %0, %0, %1;" : "+r"(a) : "r"(b))

__device__ __forceinline__ uint32_t pack2h(float a, float b) {
    __half2 t = __floats2half2_rn(a, b);
    return *(uint32_t*)&t;
}

#define QSCALE 0.18033688f   // 0.125 * log2(e), folded into Q at QKV epilogue

// ---------------------------------------------------------------------------
// Fused conversion kernel (one launch): x -> fp16, Wqkv/Wproj -> fp16 [N,K]
// ---------------------------------------------------------------------------
__global__ __launch_bounds__(256) void cvt_all(
    const float4* __restrict__ x4, uint32_t* __restrict__ xh,
    const float* __restrict__ Wq, __half* __restrict__ wqT,
    const float* __restrict__ Wp, __half* __restrict__ wpT)
{
    __shared__ float t[32][33];
    const int bx = blockIdx.x;
    if (bx < 4096) {
        const int i = bx * 256 + threadIdx.x;
        float4 v = x4[i];
        xh[2 * i + 0] = pack2h(v.x, v.y);
        xh[2 * i + 1] = pack2h(v.z, v.w);
        return;
    }
    const float* W;
    __half* WT;
    int n0, k0, N;
    if (bx < 7168) {
        const int b2 = bx - 4096;
        W = Wq; WT = wqT; N = 3072;
        n0 = (b2 % 96) * 32; k0 = (b2 / 96) * 32;
    } else {
        const int b3 = bx - 7168;
        W = Wp; WT = wpT; N = 1024;
        n0 = (b3 % 32) * 32; k0 = (b3 / 32) * 32;
    }
    const int tx = threadIdx.x & 31, ty = threadIdx.x >> 5;  // 32 x 8
#pragma unroll
    for (int i = 0; i < 32; i += 8)
        t[ty + i][tx] = W[(size_t)(k0 + ty + i) * N + n0 + tx];
    __syncthreads();
#pragma unroll
    for (int i = 0; i < 32; i += 8)
        WT[(size_t)(n0 + ty + i) * 1024 + k0 + tx] = __float2half_rn(t[tx][ty + i]);
}

// ---------------------------------------------------------------------------
// fp16 single-pass GEMM: C = A[M,K] @ B[N,K]^T + bias; cols < qcols get the
// softmax pre-scale QSCALE folded in. (Unchanged from R14-R16.)
// 128x128 tile, BK=64, 8 warps (warp tile 32x64), 3-stage cp.async, ldmatrix.
// ---------------------------------------------------------------------------
#define GM_BPLANE   18432                    // A plane: 128 rows * 144
#define GM_STAGE    36864                    // A + B planes
#define GEMM_SMEM   (3 * GM_STAGE)           // 110,592

template<bool OUT_HALF>
__global__ __launch_bounds__(256, 2) void gemm_mma(
    const __half* __restrict__ A, const __half* __restrict__ Bh,
    const float* __restrict__ bias, float* __restrict__ C,
    __half* __restrict__ Ch,
    int M, int N, int K, int qcols)
{
    extern __shared__ __align__(16) char smem[];
    const uint32_t sbase = smem_u32(smem);

    const int tid = threadIdx.x;
    const int wid = tid >> 5, lane = tid & 31;
    const int g = lane >> 2, t4 = lane & 3;
    const int wm = wid & 3, wn = wid >> 2;          // 4 x 2 warp grid
    const int m0 = blockIdx.y * 128, n0 = blockIdx.x * 128;

    const char* srcp[8];
    uint32_t dsto[8];
#pragma unroll
    for (int i = 0; i < 8; i++) {
        const int c = tid + 256 * i;
        const int mat = c >> 10;                // 0=A, 1=B
        const int cc = c & 1023;
        const int row = cc >> 3, q = cc & 7;
        dsto[i] = mat * GM_BPLANE + row * 144 + q * 16;
        const __half* bp = mat ? Bh : A;
        const int grow = mat ? (n0 + row) : (m0 + row);
        srcp[i] = (const char*)(bp + (size_t)grow * K) + q * 16;
    }

    float acc[2][8][4];
#pragma unroll
    for (int mt = 0; mt < 2; mt++)
#pragma unroll
        for (int nt = 0; nt < 8; nt++)
#pragma unroll
            for (int e = 0; e < 4; e++) acc[mt][nt][e] = 0.f;

    const int nk = K / 64;                      // 16
#pragma unroll
    for (int s = 0; s < 2; s++) {
#pragma unroll
        for (int i = 0; i < 8; i++)
            CPASYNC16(sbase + s * GM_STAGE + dsto[i], srcp[i] + s * 128);
        CPCOMMIT();
    }

    const uint32_t aoff = (uint32_t)((wm * 32 + (lane & 15)) * 144 + (lane >> 4) * 16);
    const uint32_t boff = (uint32_t)(GM_BPLANE
        + (wn * 64 + (lane & 7) + ((lane >> 4) & 1) * 8) * 144
        + ((lane >> 3) & 1) * 16);

    for (int kc = 0; kc < nk; kc++) {
        CPWAIT(1);            // stage kc landed
        __syncthreads();
        if (kc + 2 < nk) {
            const uint32_t sb = sbase + ((kc + 2) % 3) * GM_STAGE;
#pragma unroll
            for (int i = 0; i < 8; i++)
                CPASYNC16(sb + dsto[i], srcp[i] + (size_t)(kc + 2) * 128);
        }
        CPCOMMIT();

        const uint32_t stg = sbase + (kc % 3) * GM_STAGE;
#pragma unroll
        for (int u = 0; u < 4; u++) {
            uint32_t ah[2][4], bh[8][2];
#pragma unroll
            for (int mt = 0; mt < 2; mt++)
                LDMX4(ah[mt], stg + aoff + mt * 2304 + u * 32);
#pragma unroll
            for (int p = 0; p < 4; p++) {
                uint32_t th[4];
                LDMX4(th, stg + boff + p * 2304 + u * 32);
                bh[2 * p][0] = th[0]; bh[2 * p][1] = th[1];
                bh[2 * p + 1][0] = th[2]; bh[2 * p + 1][1] = th[3];
            }
#pragma unroll
            for (int mt = 0; mt < 2; mt++)
#pragma unroll
                for (int nt = 0; nt < 8; nt++) mma_f16(acc[mt][nt], ah[mt], bh[nt]);
        }
    }

#pragma unroll
    for (int mt = 0; mt < 2; mt++) {
        const int row0 = m0 + wm * 32 + mt * 16 + g;
#pragma unroll
        for (int nt = 0; nt < 8; nt++) {
            const int col = n0 + wn * 64 + nt * 8 + 2 * t4;
            const float sc = (col < qcols) ? QSCALE : 1.f;
            const float b0 = bias[col], b1 = bias[col + 1];
            const float v00 = (acc[mt][nt][0] + b0) * sc, v01 = (acc[mt][nt][1] + b1) * sc;
            const float v10 = (acc[mt][nt][2] + b0) * sc, v11 = (acc[mt][nt][3] + b1) * sc;
            if (OUT_HALF) {
                *(uint32_t*)(Ch + (size_t)row0 * N + col) = pack2h(v00, v01);
                *(uint32_t*)(Ch + (size_t)(row0 + 8) * N + col) = pack2h(v10, v11);
            } else {
                *(float2*)(C + (size_t)row0 * N + col) = make_float2(v00, v01);
                *(float2*)(C + (size_t)(row0 + 8) * N + col) = make_float2(v10, v11);
            }
        }
    }
}

// ---------------------------------------------------------------------------
// Flash attention, fp16 S path, 128 threads (4 warps), q-tile 64, 4 CTAs/SM.
// 3-stage KV ring (Q lands in b2 first, consumed to registers, b2 rejoins).
// S = Q'K^T (fp16 acc, Q pre-scaled) -> ex2.f16x2 -> mask-mult (diag only).
// NEW vs R16:
//  * Row sums: the 4 per-u ones-MMAs are merged into ONE per stage by
//    pre-adding the P fragments with add.f16x2 (B==1 => sums commute).
//  * Diagonal stage (st==qt): p-tiles with p > wid are fully causal-masked
//    for this warp -> skip their S-MMAs, ex2, and PV-MMAs (P==0 exactly,
//    so dropped PV terms are +0 adds; O is bit-identical). Mask multiply
//    restricted to the single partial pair nt = 2*wid, 2*wid+1.
// ---------------------------------------------------------------------------
#define A_KPLANE   9216                  // 64 rows * 144 (K plane; V at +9216)
#define A_KVSTAGE  18432                 // K plane + V plane
#define ATTN_SMEM  (3 * A_KVSTAGE)       // 55,296

__global__ __launch_bounds__(128, 4) void attn_mma(
    const __half* __restrict__ qkv_g, __half* __restrict__ o_g)
{
    extern __shared__ __align__(16) char smem[];
    const uint32_t sbase = smem_u32(smem);

    const int tid = threadIdx.x;
    const int wid = tid >> 5, lane = tid & 31;    // wid 0..3
    const int g = lane >> 2, t4 = lane & 3;
    const int qt = (int)gridDim.x - 1 - (int)blockIdx.x;
    const int h = blockIdx.y, b = blockIdx.z;
    const int q0 = qt * 64;
    const int nst = qt + 1;              // 64-k stages
    const size_t bL = (size_t)b * L_;

    // KV descriptors: per stage K 512 + V 512 chunks = 1024 => 8/thread
    uint32_t kv_dsto[8];
    int kv_row[8], kv_goff[8];
#pragma unroll
    for (int i = 0; i < 8; i++) {
        const int c = tid + 128 * i;
        const int mat = c >> 9;            // 0=K, 1=V
        const int cc = c & 511;
        const int row = cc >> 3, q = cc & 7;
        kv_dsto[i] = mat * A_KPLANE + row * 144 + q * 16;
        kv_goff[i] = 1024 + mat * 1024 + h * 64 + q * 8;
        kv_row[i] = row;                   // 0..63
    }

    // prologue: Gq = Q tile into ring buffer b2; G0 = KV st0; G1 = KV st1.
#pragma unroll
    for (int i = 0; i < 4; i++) {
        const int c = tid + 128 * i;
        const int row = c >> 3, q = c & 7;
        CPASYNC16(sbase + 2 * A_KVSTAGE + row * 144 + q * 16,
                  qkv_g + (bL + q0 + row) * 3072 + h * 64 + q * 8);
    }
    CPCOMMIT();   // Gq
#pragma unroll
    for (int i = 0; i < 8; i++)
        CPASYNC16(sbase + kv_dsto[i],
                  qkv_g + (bL + kv_row[i]) * 3072 + kv_goff[i]);
    CPCOMMIT();   // G0
#pragma unroll
    for (int i = 0; i < 8; i++)
        CPASYNC16(sbase + A_KVSTAGE + kv_dsto[i],
                  qkv_g + (bL + 64 + kv_row[i]) * 3072 + kv_goff[i]);
    CPCOMMIT();   // G1

    const uint32_t qoff = (uint32_t)(2 * A_KVSTAGE
        + (wid * 16 + (lane & 15)) * 144 + (lane >> 4) * 16);
    const uint32_t koff = (uint32_t)(((lane & 7) + ((lane >> 4) & 1) * 8) * 144
                                     + ((lane >> 3) & 1) * 16);
    const int m4 = lane >> 3;
    const int vrow = (m4 & 1) * 8 + (lane & 7);
    const int vcol = (m4 >> 1) * 8;
    const uint32_t ones2 = 0x3C003C00u;   // half2 {1.0, 1.0}
    uint32_t onesb[2] = {ones2, ones2};

    // consume Q into registers before the loop; b2 then joins the KV ring
    uint32_t qf[4][4];
    CPWAIT(2);            // Gq landed; G0,G1 may be in flight
    __syncthreads();      // publish all threads' Q chunks
#pragma unroll
    for (int u = 0; u < 4; u++)
        LDMX4(qf[u], sbase + qoff + u * 32);

    float of[8][4];
    float lsum[4] = {0.f, 0.f, 0.f, 0.f};   // merged-ones-MMA row sums
#pragma unroll
    for (int nt = 0; nt < 8; nt++)
#pragma unroll
        for (int e = 0; e < 4; e++) of[nt][e] = 0.f;

    const int wqmax = q0 + wid * 16 + 15;

    for (int st = 0; st < nst; st++) {
        CPWAIT(1);           // stage st landed
        __syncthreads();     // all copies visible; Q reads (pre-loop) done
        if (st + 2 < nst) {
            const uint32_t sb = sbase + ((st + 2) % 3) * A_KVSTAGE;
            const size_t rbase = bL + (size_t)(st + 2) * 64;
#pragma unroll
            for (int i = 0; i < 8; i++)
                CPASYNC16(sb + kv_dsto[i], qkv_g + (rbase + kv_row[i]) * 3072 + kv_goff[i]);
        }
        CPCOMMIT();          // unconditional: keeps group-count invariant

        const int k0 = st * 64;
        if (k0 > wqmax) continue;   // fully-masked stage for this warp

        const bool diag = (k0 + 63 > q0 + wid * 16);   // st == qt
        const int pmax = diag ? wid : 3;               // active p/u tiles

        const uint32_t stg = sbase + (st % 3) * A_KVSTAGE;

        // S = Q' K^T with fp16 accumulators; sh[nt] = {row g, row g+8}.
        // Skipped p-tiles (diag, p > wid) stay 0 and never go through ex2.
        uint32_t sh[8][2];
#pragma unroll
        for (int nt = 0; nt < 8; nt++) { sh[nt][0] = 0u; sh[nt][1] = 0u; }

#pragma unroll
        for (int u = 0; u < 4; u++) {
#pragma unroll
            for (int p = 0; p < 4; p++) {
                if (p > pmax) break;
                uint32_t th[4];
                LDMX4(th, stg + koff + p * 2304 + u * 32);
                mma_f16h(sh[2 * p], qf[u], th);
                mma_f16h(sh[2 * p + 1], qf[u], th + 2);
            }
        }

        // P = 2^S for active tiles only
#pragma unroll
        for (int nt = 0; nt < 8; nt++) {
            if (nt > 2 * pmax + 1) break;
            EX2F16X2(sh[nt][0]);
            EX2F16X2(sh[nt][1]);
        }
        // mask: only the partial pair nt = 2*wid, 2*wid+1 (p < wid unmasked)
        if (diag) {
            const int qr0 = q0 + wid * 16 + g;
#pragma unroll
            for (int j = 0; j < 2; j++) {
                const int nt = 2 * wid + j;
                const int col = k0 + nt * 8 + 2 * t4;
                const uint32_t mk0 = (col <= qr0 ? 0x3C00u : 0u)
                                   | (col + 1 <= qr0 ? 0x3C000000u : 0u);
                const uint32_t mk1 = (col <= qr0 + 8 ? 0x3C00u : 0u)
                                   | (col + 1 <= qr0 + 8 ? 0x3C000000u : 0u);
                HMUL2(sh[nt][0], mk0);
                HMUL2(sh[nt][1], mk1);
            }
        }

        // merged row sum: tr = sum_u P_u fragments (f16 adds), ONE ones-MMA.
        // Skipped tiles contribute exact 0 (never ex2'd).
        {
            uint32_t tr[4];
            tr[0] = sh[0][0]; tr[1] = sh[0][1];
            tr[2] = sh[1][0]; tr[3] = sh[1][1];
#pragma unroll
            for (int u = 1; u < 4; u++) {
                if (u > pmax) break;
                HADD2(tr[0], sh[2 * u][0]);
                HADD2(tr[1], sh[2 * u][1]);
                HADD2(tr[2], sh[2 * u + 1][0]);
                HADD2(tr[3], sh[2 * u + 1][1]);
            }
            mma_f16(lsum, tr, onesb);
        }

        // PV: f16 D-fragments ARE the PV A-fragments; skip all-zero u tiles
        const uint32_t vbase = stg + A_KPLANE;
#pragma unroll
        for (int u = 0; u < 4; u++) {
            if (u > pmax) break;
            uint32_t ph[4];
            ph[0] = sh[2 * u][0];
            ph[1] = sh[2 * u][1];
            ph[2] = sh[2 * u + 1][0];
            ph[3] = sh[2 * u + 1][1];
#pragma unroll
            for (int ntp = 0; ntp < 4; ntp++) {
                const uint32_t addr = vbase + (16 * u + vrow) * 144
                                    + (ntp * 16 + vcol) * 2;
                uint32_t r0, r1, r2, r3;
                LDMX4_TRANS(r0, r1, r2, r3, addr);
                uint32_t bb[2];
                bb[0] = r0; bb[1] = r1;
                mma_f16(of[2 * ntp], ph, bb);
                bb[0] = r2; bb[1] = r3;
                mma_f16(of[2 * ntp + 1], ph, bb);
            }
        }
    }

    CPWAIT(0);   // drain any unconsumed prefetch groups before exit

    // epilogue: lsum holds full row sums in every lane
    const float inv0 = 1.f / lsum[0], inv1 = 1.f / lsum[2];
    const int qr0 = q0 + wid * 16 + g;
#pragma unroll
    for (int nt = 0; nt < 8; nt++) {
        const int col = h * 64 + nt * 8 + 2 * t4;
        *(uint32_t*)(o_g + (bL + qr0) * D_ + col) =
            pack2h(of[nt][0] * inv0, of[nt][1] * inv0);
        *(uint32_t*)(o_g + (bL + qr0 + 8) * D_ + col) =
            pack2h(of[nt][2] * inv1, of[nt][3] * inv1);
    }
}

// ---------------------------------------------------------------------------
extern "C" void kernel_launch(void* const* d_in, const int* in_sizes, int n_in,
                              void* d_out, int out_size)
{
    const float* x     = (const float*)d_in[0];
    const float* Wqkv  = (const float*)d_in[1];
    const float* bqkv  = (const float*)d_in[2];
    const float* Wproj = (const float*)d_in[3];
    const float* bproj = (const float*)d_in[4];
    float* out = (float*)d_out;

    __half *xh, *qk, *ah, *wq, *wp;
    cudaGetSymbolAddress((void**)&xh, g_x);
    cudaGetSymbolAddress((void**)&qk, g_qkv);
    cudaGetSymbolAddress((void**)&ah, g_attn);
    cudaGetSymbolAddress((void**)&wq, g_wqkv);
    cudaGetSymbolAddress((void**)&wp, g_wproj);

    cudaFuncSetAttribute(gemm_mma<true>,  cudaFuncAttributeMaxDynamicSharedMemorySize, GEMM_SMEM);
    cudaFuncSetAttribute(gemm_mma<false>, cudaFuncAttributeMaxDynamicSharedMemorySize, GEMM_SMEM);
    cudaFuncSetAttribute(attn_mma, cudaFuncAttributeMaxDynamicSharedMemorySize, ATTN_SMEM);

    // 0) fused precision conversions (one launch)
    cvt_all<<<8192, 256>>>((const float4*)x, (uint32_t*)xh, Wqkv, wq, Wproj, wp);

    // 1) QKV projection -> fp16 qkv (Q columns pre-scaled by 0.125*log2e)
    gemm_mma<true><<<dim3((3 * D_) / 128, MTOK / 128), 256, GEMM_SMEM>>>(
        xh, wq, bqkv, nullptr, qk, MTOK, 3 * D_, D_, D_);

    // 2) causal flash attention -> fp16 (q-tile 64, 4 warps, 3-stage ring)
    attn_mma<<<dim3(L_ / 64, H_, B_), 128, ATTN_SMEM>>>(qk, ah);

    // 3) output projection -> fp32 out
    gemm_mma<false><<<dim3(D_ / 128, MTOK / 128), 256, GEMM_SMEM>>>(
        ah, wp, bproj, out, nullptr, MTOK, D_, D_, 0);
}